// round 1
// baseline (speedup 1.0000x reference)
#include <cuda_runtime.h>
#include <cuda_fp16.h>
#include <cstdint>

#define HW 4096
#define D  64
#define BATCH 4
#define TM 64
#define TK 64
#define NCHUNK (HW / TK)
#define AS_STRIDE 80   // 64 + 16 halves pad: keeps 16B alignment, spreads ldmatrix banks
#define FS_STRIDE 80
#define CS_STRIDE 66

// Precomputed positional encoding f[m][d] in fp16 (512 KB, L2-resident).
__device__ __half g_f[HW * D];

__device__ __forceinline__ uint32_t sptr(const void* p) {
    return (uint32_t)__cvta_generic_to_shared(p);
}

// ---------------------------------------------------------------------------
// Kernel 1: f[m,d] = cos(8*pi*(w[d,0]*gx + w[d,1]*gy + b[d])), m = y*64 + x
// ---------------------------------------------------------------------------
__global__ void pos_enc_kernel(const float* __restrict__ w,
                               const float* __restrict__ bias) {
    int idx = blockIdx.x * blockDim.x + threadIdx.x;
    if (idx >= HW * D) return;
    int d = idx & (D - 1);
    int m = idx >> 6;
    int x = m & 63;
    int y = m >> 6;
    float gx = (float)(2 * x - 63) * (1.0f / 64.0f);  // linspace(-63/64, 63/64, 64)
    float gy = (float)(2 * y - 63) * (1.0f / 64.0f);
    float proj = fmaf(w[2 * d], gx, fmaf(w[2 * d + 1], gy, bias[d]));
    g_f[idx] = __float2half_rn(cosf(25.132741228718345f * proj));  // 8*pi
}

// ---------------------------------------------------------------------------
// Kernel 2: fused exp + row-sum + skinny GEMM (mma.sync fp16) + divide + transpose
// One CTA = 64 rows of one batch. K loop over 4096 in chunks of 64.
// ---------------------------------------------------------------------------
struct __align__(16) Smem {
    union {
        struct {
            __half As[TM * AS_STRIDE];   // exp(sim) chunk, fp16
            __half Fs[TK * FS_STRIDE];   // f chunk, fp16
        } ab;
        float Cs[TM * CS_STRIDE];        // epilogue transpose staging (after last sync)
    } u;
    float Zpart[TM][4];
    float Zs[TM];
};

__global__ __launch_bounds__(256, 2)
void gp_kernel(const float* __restrict__ sim, float* __restrict__ out) {
    __shared__ Smem sm;
    __half* As = sm.u.ab.As;
    __half* Fs = sm.u.ab.Fs;

    const int tid  = threadIdx.x;
    const int lane = tid & 31;
    const int warp = tid >> 5;
    const int wm   = warp & 3;    // M16 tile index (rows wm*16..)
    const int wn   = warp >> 2;   // N32 half (cols wn*32..)
    const int lrow = tid >> 2;    // 0..63 : row handled by this thread for loads
    const int lseg = tid & 3;     // 0..3  : 16-col segment within chunk

    const int bb   = blockIdx.y;
    const int row0 = blockIdx.x * TM;

    const float* gA = sim + ((size_t)bb * HW + row0 + lrow) * HW + lseg * 16;

    float acc[4][4];
#pragma unroll
    for (int i = 0; i < 4; i++)
#pragma unroll
        for (int j = 0; j < 4; j++) acc[i][j] = 0.0f;

    float zpart = 0.0f;

    // Preload first sim chunk (16 floats / thread)
    float4 v0 = *(const float4*)(gA + 0);
    float4 v1 = *(const float4*)(gA + 4);
    float4 v2 = *(const float4*)(gA + 8);
    float4 v3 = *(const float4*)(gA + 12);

    for (int kc = 0; kc < NCHUNK; kc++) {
        // ---- exp + pack to fp16 smem + row-sum ----
        {
            __half2* ar = (__half2*)&As[lrow * AS_STRIDE + lseg * 16];
            float e0, e1, s = 0.0f;
            e0 = __expf(v0.x); e1 = __expf(v0.y); s += e0 + e1; ar[0] = __floats2half2_rn(e0, e1);
            e0 = __expf(v0.z); e1 = __expf(v0.w); s += e0 + e1; ar[1] = __floats2half2_rn(e0, e1);
            e0 = __expf(v1.x); e1 = __expf(v1.y); s += e0 + e1; ar[2] = __floats2half2_rn(e0, e1);
            e0 = __expf(v1.z); e1 = __expf(v1.w); s += e0 + e1; ar[3] = __floats2half2_rn(e0, e1);
            e0 = __expf(v2.x); e1 = __expf(v2.y); s += e0 + e1; ar[4] = __floats2half2_rn(e0, e1);
            e0 = __expf(v2.z); e1 = __expf(v2.w); s += e0 + e1; ar[5] = __floats2half2_rn(e0, e1);
            e0 = __expf(v3.x); e1 = __expf(v3.y); s += e0 + e1; ar[6] = __floats2half2_rn(e0, e1);
            e0 = __expf(v3.z); e1 = __expf(v3.w); s += e0 + e1; ar[7] = __floats2half2_rn(e0, e1);
            zpart += s;
        }

        // ---- load f chunk (L2-resident) ----
        {
            const uint4* fp = (const uint4*)(g_f + (((size_t)kc * TK + lrow) << 6) + lseg * 16);
            uint4 q0 = fp[0];
            uint4 q1 = fp[1];
            *(uint4*)&Fs[lrow * FS_STRIDE + lseg * 16]     = q0;
            *(uint4*)&Fs[lrow * FS_STRIDE + lseg * 16 + 8] = q1;
        }

        __syncthreads();

        // ---- prefetch next sim chunk (overlaps MMA below) ----
        if (kc + 1 < NCHUNK) {
            gA += TK;
            v0 = *(const float4*)(gA + 0);
            v1 = *(const float4*)(gA + 4);
            v2 = *(const float4*)(gA + 8);
            v3 = *(const float4*)(gA + 12);
        }

        // ---- MMA: warp computes 16 (M) x 32 (N), K=64 ----
#pragma unroll
        for (int ks = 0; ks < 4; ks++) {
            uint32_t a0, a1, a2, a3;
            uint32_t aaddr = sptr(&As[(wm * 16 + (lane & 15)) * AS_STRIDE +
                                      ks * 16 + ((lane >> 4) << 3)]);
            asm volatile("ldmatrix.sync.aligned.m8n8.x4.shared.b16 {%0,%1,%2,%3}, [%4];\n"
                         : "=r"(a0), "=r"(a1), "=r"(a2), "=r"(a3) : "r"(aaddr));
#pragma unroll
            for (int nh = 0; nh < 2; nh++) {
                uint32_t b0, b1, b2, b3;
                uint32_t baddr = sptr(&Fs[(ks * 16 + (lane & 15)) * FS_STRIDE +
                                          wn * 32 + nh * 16 + ((lane >> 4) << 3)]);
                asm volatile("ldmatrix.sync.aligned.m8n8.x4.trans.shared.b16 {%0,%1,%2,%3}, [%4];\n"
                             : "=r"(b0), "=r"(b1), "=r"(b2), "=r"(b3) : "r"(baddr));
                asm volatile("mma.sync.aligned.m16n8k16.row.col.f32.f16.f16.f32 "
                             "{%0,%1,%2,%3}, {%4,%5,%6,%7}, {%8,%9}, {%0,%1,%2,%3};\n"
                             : "+f"(acc[2 * nh][0]), "+f"(acc[2 * nh][1]),
                               "+f"(acc[2 * nh][2]), "+f"(acc[2 * nh][3])
                             : "r"(a0), "r"(a1), "r"(a2), "r"(a3), "r"(b0), "r"(b1));
                asm volatile("mma.sync.aligned.m16n8k16.row.col.f32.f16.f16.f32 "
                             "{%0,%1,%2,%3}, {%4,%5,%6,%7}, {%8,%9}, {%0,%1,%2,%3};\n"
                             : "+f"(acc[2 * nh + 1][0]), "+f"(acc[2 * nh + 1][1]),
                               "+f"(acc[2 * nh + 1][2]), "+f"(acc[2 * nh + 1][3])
                             : "r"(a0), "r"(a1), "r"(a2), "r"(a3), "r"(b2), "r"(b3));
            }
        }
        __syncthreads();
    }

    // ---- epilogue: row-sum reduce, transpose via smem, divide, store ----
    sm.Zpart[lrow][lseg] = zpart;
    __syncthreads();

    float* Cs = sm.u.Cs;  // safe: union region, all As/Fs reads completed
    {
        int crow  = wm * 16 + (lane >> 2);
        int ccol0 = wn * 32 + (lane & 3) * 2;
#pragma unroll
        for (int nt = 0; nt < 4; nt++) {
            *(float2*)&Cs[crow * CS_STRIDE + ccol0 + nt * 8] =
                make_float2(acc[nt][0], acc[nt][1]);
            *(float2*)&Cs[(crow + 8) * CS_STRIDE + ccol0 + nt * 8] =
                make_float2(acc[nt][2], acc[nt][3]);
        }
    }
    if (tid < TM) {
        float z = sm.Zpart[tid][0] + sm.Zpart[tid][1] +
                  sm.Zpart[tid][2] + sm.Zpart[tid][3];
        sm.Zs[tid] = 1.0f / z;
    }
    __syncthreads();

    {
        const int d = tid >> 2;  // output channel
        float* go = out + ((size_t)bb * D + d) * HW + row0 + lseg * 16;
#pragma unroll
        for (int i = 0; i < 4; i++) {
            int n = lseg * 16 + i * 4;
            float4 o;
            o.x = Cs[(n + 0) * CS_STRIDE + d] * sm.Zs[n + 0];
            o.y = Cs[(n + 1) * CS_STRIDE + d] * sm.Zs[n + 1];
            o.z = Cs[(n + 2) * CS_STRIDE + d] * sm.Zs[n + 2];
            o.w = Cs[(n + 3) * CS_STRIDE + d] * sm.Zs[n + 3];
            *(float4*)(go + i * 4) = o;
        }
    }
}

// ---------------------------------------------------------------------------
extern "C" void kernel_launch(void* const* d_in, const int* in_sizes, int n_in,
                              void* d_out, int out_size) {
    const float* sim  = (const float*)d_in[0];  // [4, 4096, 4096] fp32
    const float* w    = (const float*)d_in[1];  // [64, 2] fp32
    const float* bias = (const float*)d_in[2];  // [64] fp32
    float* out = (float*)d_out;                 // [4, 64, 64, 64] fp32

    pos_enc_kernel<<<(HW * D + 255) / 256, 256>>>(w, bias);

    dim3 grid(HW / TM, BATCH);
    gp_kernel<<<grid, 256>>>(sim, out);
}